// round 1
// baseline (speedup 1.0000x reference)
#include <cuda_runtime.h>
#include <cuda_bf16.h>

#define KDIM 64
#define MAXB 1024

// per-batch partial results (fwd - gold), reduced by second kernel
__device__ float g_partial[MAXB];

// One block per batch. 64 threads; thread j owns CRF state column j.
// Forward recursion in linear space:
//   nxt[j] = m + log( sum_i exp(alpha[i]-m) * E[i][j] ) + emit[t][j],
//   E = exp(transitions) held in registers (column j per thread).
// m = alpha[0] broadcast (spread of alpha is bounded by emission spread; safe).
__global__ __launch_bounds__(64, 8)
void crf_forward_kernel(const float* __restrict__ emis,
                        const float* __restrict__ trans,
                        const float* __restrict__ start_t,
                        const float* __restrict__ end_t,
                        const int*  __restrict__ labels,
                        const int*  __restrict__ sent_len,
                        int T)
{
    const int b = blockIdx.x;
    const int j = threadIdx.x;
    const int L = sent_len[b];
    const float* em  = emis   + (size_t)b * T * KDIM;
    const int*   lab = labels + (size_t)b * T;

    __shared__ __align__(16) float sa[KDIM];
    __shared__ float sh_m;
    __shared__ float rmax[2], rsum[2], rgold[2];

    // E column j -> registers (constant over time)
    float Ecol[KDIM];
#pragma unroll
    for (int i = 0; i < KDIM; ++i)
        Ecol[i] = __expf(trans[i * KDIM + j]);

    // t = 0
    float alpha = start_t[j] + em[j];
    float gold  = 0.0f;
    int lab_prev = lab[0];
    if (j == lab_prev) gold = alpha;          // start[lab0] + emit[0][lab0]

    if (j == 0) sh_m = alpha;
    float e_next = em[KDIM + j];              // prefetch t=1 row (T >= 2)
    __syncthreads();
    float m = sh_m;

    for (int t = 1; t < L; ++t) {
        const float e_cur = e_next;
        const int tn = (t + 1 < T) ? (t + 1) : t;
        e_next = em[(size_t)tn * KDIM + j];   // prefetch next step
        const int lab_t = lab[t];             // broadcast LDG

        sa[j] = __expf(alpha - m);
        __syncthreads();

        float s0 = 0.f, s1 = 0.f, s2 = 0.f, s3 = 0.f;
        const float4* sa4 = (const float4*)sa;
#pragma unroll
        for (int i4 = 0; i4 < KDIM / 4; ++i4) {
            const float4 v = sa4[i4];
            s0 = fmaf(v.x, Ecol[4 * i4 + 0], s0);
            s1 = fmaf(v.y, Ecol[4 * i4 + 1], s1);
            s2 = fmaf(v.z, Ecol[4 * i4 + 2], s2);
            s3 = fmaf(v.w, Ecol[4 * i4 + 3], s3);
        }
        const float s = (s0 + s1) + (s2 + s3);
        const float nxt = m + __logf(s) + e_cur;

        if (j == lab_t)
            gold += e_cur + trans[lab_prev * KDIM + j];
        lab_prev = lab_t;

        if (j == 0) sh_m = nxt;               // safe: old sh_m already consumed
        alpha = nxt;
        __syncthreads();
        m = sh_m;
    }

    // gold end term: lab_prev == labels[L-1]
    if (j == lab_prev) gold += end_t[j];

    // fwd = logsumexp(alpha + end)
    const float x = alpha + end_t[j];
    float wm = x;
#pragma unroll
    for (int o = 16; o; o >>= 1) wm = fmaxf(wm, __shfl_xor_sync(0xffffffffu, wm, o));
    if ((j & 31) == 0) rmax[j >> 5] = wm;
    __syncthreads();
    const float mx = fmaxf(rmax[0], rmax[1]);

    float ex = __expf(x - mx);
    float gg = gold;
#pragma unroll
    for (int o = 16; o; o >>= 1) {
        ex += __shfl_xor_sync(0xffffffffu, ex, o);
        gg += __shfl_xor_sync(0xffffffffu, gg, o);
    }
    if ((j & 31) == 0) { rsum[j >> 5] = ex; rgold[j >> 5] = gg; }
    __syncthreads();

    if (j == 0) {
        const float fwd = mx + __logf(rsum[0] + rsum[1]);
        g_partial[b] = fwd - (rgold[0] + rgold[1]);
    }
}

// Deterministic final reduction: out = sum(partial)/B
__global__ void crf_reduce_kernel(float* __restrict__ out, int B)
{
    __shared__ float ws[16];
    const int tid = threadIdx.x;
    float v = 0.0f;
    for (int i = tid; i < B; i += blockDim.x) v += g_partial[i];
#pragma unroll
    for (int o = 16; o; o >>= 1) v += __shfl_xor_sync(0xffffffffu, v, o);
    const int warp = tid >> 5;
    if ((tid & 31) == 0) ws[warp] = v;
    __syncthreads();
    if (tid < 16) {
        float u = (tid < (blockDim.x + 31) / 32) ? ws[tid] : 0.0f;
#pragma unroll
        for (int o = 8; o; o >>= 1) u += __shfl_xor_sync(0x0000ffffu, u, o);
        if (tid == 0) out[0] = u / (float)B;
    }
}

extern "C" void kernel_launch(void* const* d_in, const int* in_sizes, int n_in,
                              void* d_out, int out_size)
{
    // metadata order: emissions, transitions, start_trans, end_trans, labels, sent_len
    const float* emis    = (const float*)d_in[0];
    const float* trans   = (const float*)d_in[1];
    const float* start_t = (const float*)d_in[2];
    const float* end_t   = (const float*)d_in[3];
    const int*   labels  = (const int*)d_in[4];
    const int*   slen    = (const int*)d_in[5];

    const int B = in_sizes[5];                // 512
    const int T = in_sizes[4] / B;            // 1024
    float* out = (float*)d_out;

    crf_forward_kernel<<<B, KDIM>>>(emis, trans, start_t, end_t, labels, slen, T);
    crf_reduce_kernel<<<1, 512>>>(out, B);
}

// round 3
// speedup vs baseline: 1.7071x; 1.7071x over previous
#include <cuda_runtime.h>
#include <cuda_bf16.h>

#define KDIM 64
#define MAXB 1024
#define PF   4   // prefetch depth (steps)

__device__ float g_partial[MAXB];

typedef unsigned long long ull;

__device__ __forceinline__ void fma2(ull& acc, ull a, ull b) {
    asm("fma.rn.f32x2 %0, %1, %2, %3;" : "=l"(acc) : "l"(a), "l"(b), "l"(acc));
}
__device__ __forceinline__ void add2(ull& d, ull a, ull b) {
    asm("add.rn.f32x2 %0, %1, %2;" : "=l"(d) : "l"(a), "l"(b));
}

// One block per batch; thread j owns CRF state column j.
// Linear-space recursion: nxt[j] = m + log( sum_i exp(alpha[i]-m)*E[i][j] ) + emit[t][j]
// with E = exp(trans) in registers (packed f32x2 pairs over i), a LAGGED uniform
// shift m (alpha_0 from the previous step; exp args bounded, fp32-safe),
// one __syncthreads per step (double-buffered sa), and 4-deep prefetch of
// emissions/labels to hide DRAM latency.
__global__ __launch_bounds__(64, 8)
void crf_forward_kernel(const float* __restrict__ emis,
                        const float* __restrict__ trans,
                        const float* __restrict__ start_t,
                        const float* __restrict__ end_t,
                        const int*  __restrict__ labels,
                        const int*  __restrict__ sent_len,
                        int T)
{
    const int b = blockIdx.x;
    const int j = threadIdx.x;
    const int L = sent_len[b];
    const float* em  = emis   + (size_t)b * T * KDIM;
    const int*   lab = labels + (size_t)b * T;

    __shared__ __align__(16) float sa[2][KDIM];
    __shared__ float sm[2];
    __shared__ float rmax[2], rsum[2], rgold[2];

    // E column j as 32 packed (even,odd) f32x2 pairs -> 64 regs
    ull Epk[KDIM / 2];
#pragma unroll
    for (int i2 = 0; i2 < KDIM / 2; ++i2) {
        const float lo = __expf(trans[(2 * i2)     * KDIM + j]);
        const float hi = __expf(trans[(2 * i2 + 1) * KDIM + j]);
        Epk[i2] = (ull)__float_as_uint(lo) | ((ull)__float_as_uint(hi) << 32);
    }

    // t = 0
    float alpha = start_t[j] + em[j];
    float gold  = 0.0f;
    int lab_prev = lab[0];
    if (j == lab_prev) gold = alpha;      // start[lab0] + emit[0][lab0]

    float m = 0.0f;                       // initial uniform shift (alpha ~ ±10, safe)
    int buf = 0;

    // recursion step as a lambda (proper scoping — no macro capture hazards)
    auto step = [&](float ecur, int labt) {
        // gold trans term: LDG issued early, off the alpha chain
        if (j == labt) gold += ecur + trans[lab_prev * KDIM + j];
        lab_prev = labt;
        sa[buf][j] = __expf(alpha - m);
        if (j == 0) sm[buf] = alpha;      // next step's shift
        __syncthreads();
        const float mnew = sm[buf];
        ull a0 = 0ull, a1 = 0ull, a2 = 0ull, a3 = 0ull;
        const ulonglong2* sv = (const ulonglong2*)sa[buf];
#pragma unroll
        for (int q = 0; q < 8; ++q) {
            const ulonglong2 v0 = sv[2 * q];
            const ulonglong2 v1 = sv[2 * q + 1];
            fma2(a0, v0.x, Epk[4 * q + 0]);
            fma2(a1, v0.y, Epk[4 * q + 1]);
            fma2(a2, v1.x, Epk[4 * q + 2]);
            fma2(a3, v1.y, Epk[4 * q + 3]);
        }
        add2(a0, a0, a1);
        add2(a2, a2, a3);
        add2(a0, a0, a2);
        const float s = __uint_as_float((unsigned)a0)
                      + __uint_as_float((unsigned)(a0 >> 32));
        alpha = m + __logf(s) + ecur;
        m = mnew;
        buf ^= 1;
    };

    // prefetch rings (emissions row element j, and label) for steps t=1..PF
    float eb[PF];
    int   lb[PF];
#pragma unroll
    for (int k = 0; k < PF; ++k) {
        int tt = 1 + k; if (tt > T - 1) tt = T - 1;
        eb[k] = em[(size_t)tt * KDIM + j];
        lb[k] = lab[tt];
    }

    int t = 1;
    for (; t + PF <= L; t += PF) {
#pragma unroll
        for (int k = 0; k < PF; ++k) {
            const float ec = eb[k];
            const int   lc = lb[k];
            int tp = t + PF + k; if (tp > T - 1) tp = T - 1;
            eb[k] = em[(size_t)tp * KDIM + j];   // refill ring (deep prefetch)
            lb[k] = lab[tp];
            step(ec, lc);
        }
    }
    // tail: at most PF-1 steps, data already in the ring
    for (int k = 0; t < L; ++t, ++k) {
        step(eb[k], lb[k]);
    }

    // gold end term
    if (j == lab_prev) gold += end_t[j];

    // fwd = logsumexp(alpha + end)
    const float x = alpha + end_t[j];
    float wm = x;
#pragma unroll
    for (int o = 16; o; o >>= 1) wm = fmaxf(wm, __shfl_xor_sync(0xffffffffu, wm, o));
    if ((j & 31) == 0) rmax[j >> 5] = wm;
    __syncthreads();
    const float mx = fmaxf(rmax[0], rmax[1]);

    float ex = __expf(x - mx);
    float gg = gold;
#pragma unroll
    for (int o = 16; o; o >>= 1) {
        ex += __shfl_xor_sync(0xffffffffu, ex, o);
        gg += __shfl_xor_sync(0xffffffffu, gg, o);
    }
    if ((j & 31) == 0) { rsum[j >> 5] = ex; rgold[j >> 5] = gg; }
    __syncthreads();

    if (j == 0) {
        const float fwd = mx + __logf(rsum[0] + rsum[1]);
        g_partial[b] = fwd - (rgold[0] + rgold[1]);
    }
}

// Deterministic final reduction: out = sum(partial)/B
__global__ void crf_reduce_kernel(float* __restrict__ out, int B)
{
    __shared__ float ws[16];
    const int tid = threadIdx.x;
    float v = 0.0f;
    for (int i = tid; i < B; i += blockDim.x) v += g_partial[i];
#pragma unroll
    for (int o = 16; o; o >>= 1) v += __shfl_xor_sync(0xffffffffu, v, o);
    if ((tid & 31) == 0) ws[tid >> 5] = v;
    __syncthreads();
    if (tid < 16) {
        float u = (tid < (blockDim.x + 31) / 32) ? ws[tid] : 0.0f;
#pragma unroll
        for (int o = 8; o; o >>= 1) u += __shfl_xor_sync(0x0000ffffu, u, o);
        if (tid == 0) out[0] = u / (float)B;
    }
}

extern "C" void kernel_launch(void* const* d_in, const int* in_sizes, int n_in,
                              void* d_out, int out_size)
{
    const float* emis    = (const float*)d_in[0];
    const float* trans   = (const float*)d_in[1];
    const float* start_t = (const float*)d_in[2];
    const float* end_t   = (const float*)d_in[3];
    const int*   labels  = (const int*)d_in[4];
    const int*   slen    = (const int*)d_in[5];

    const int B = in_sizes[5];            // 512
    const int T = in_sizes[4] / B;        // 1024
    float* out = (float*)d_out;

    crf_forward_kernel<<<B, KDIM>>>(emis, trans, start_t, end_t, labels, slen, T);
    crf_reduce_kernel<<<1, 512>>>(out, B);
}